// round 6
// baseline (speedup 1.0000x reference)
#include <cuda_runtime.h>

#define N_NODES 100000
#define DIM 64
#define N_EDGES 1250000
#define SCAN_BLK 1024
#define NUM_SCAN_BLKS ((N_NODES + SCAN_BLK - 1) / SCAN_BLK)   // 98

// ---------------- scratch (static device globals; no runtime allocation) ----
// zero-blob: [deg: N floats][cnt: N ints][pub: 128 ints] — one memset clears all
__device__ unsigned char g_blob[(size_t)N_NODES * 8 + 512];
__device__ float g_dinv[N_NODES];
__device__ int   g_off[N_NODES + 1];
__device__ int   g_cursor[N_NODES];
__device__ int2  g_edge[N_EDGES];          // (src, nrm-as-int) interleaved
__device__ float g_xw[(size_t)N_NODES * DIM];
__device__ float g_tmp[(size_t)N_NODES * DIM];

// ---------------- side stream for fork-join overlap (created at load time) --
struct SideStream {
    cudaStream_t s = nullptr;
    cudaEvent_t  evFork = nullptr, evJoin = nullptr;
    bool ok = false;
    SideStream() {
        ok = (cudaStreamCreateWithFlags(&s, cudaStreamNonBlocking) == cudaSuccess) &&
             (cudaEventCreateWithFlags(&evFork, cudaEventDisableTiming) == cudaSuccess) &&
             (cudaEventCreateWithFlags(&evJoin, cudaEventDisableTiming) == cudaSuccess);
    }
};
static SideStream g_ss;

// ---------------- structure-building kernels (run once per call) ------------

// degree accumulation + in-degree histogram (edge_index int32: [2, E])
__global__ void k_deg_cnt(const int* __restrict__ ei,
                          const float* __restrict__ w,
                          float* __restrict__ deg,
                          int* __restrict__ cnt, int ne) {
    int e = blockIdx.x * blockDim.x + threadIdx.x;
    if (e >= ne) return;
    int c = ei[ne + e];                // col (target)
    atomicAdd(&deg[c], w[e]);
    atomicAdd(&cnt[c], 1);
}

// single-pass scan: per-block shfl scan + publish(total+1) + spin-sum
// predecessors. 98 blocks <= 148 SMs -> all resident, no progress hazard.
// Also writes off/cursor/dinv (deg complete by now).
__global__ void __launch_bounds__(SCAN_BLK) k_scan_off(
        const int* __restrict__ cnt,
        const float* __restrict__ deg,
        int* __restrict__ pub, int n, int ne) {
    __shared__ int wsum[32];
    __shared__ int pre[128];
    int b    = blockIdx.x;
    int tid  = threadIdx.x;
    int lane = tid & 31;
    int wid  = tid >> 5;
    int gid  = b * SCAN_BLK + tid;

    int c = (gid < n) ? cnt[gid] : 0;

    // warp inclusive scan
    int v = c;
#pragma unroll
    for (int d = 1; d < 32; d <<= 1) {
        int t = __shfl_up_sync(0xFFFFFFFFu, v, d);
        if (lane >= d) v += t;
    }
    if (lane == 31) wsum[wid] = v;
    __syncthreads();
    if (wid == 0) {
        int wv = wsum[lane];
#pragma unroll
        for (int d = 1; d < 32; d <<= 1) {
            int t = __shfl_up_sync(0xFFFFFFFFu, wv, d);
            if (lane >= d) wv += t;
        }
        wsum[lane] = wv;               // inclusive warp-total prefix
    }
    __syncthreads();
    int warp_ex = (wid == 0) ? 0 : wsum[wid - 1];
    int incl = v + warp_ex;            // block-inclusive scan of cnt
    int total = wsum[31];

    // publish this block's total (+1 so 0 means "not ready")
    if (tid == 0) atomicExch(&pub[b], total + 1);

    // gather predecessor totals (value lives in the flag word: no fence needed)
    if (tid < 128) {
        int pv = 0;
        if (tid < b) {
            do { pv = atomicAdd(&pub[tid], 0); } while (pv == 0);
            pv -= 1;
        }
        pre[tid] = pv;
    }
    __syncthreads();
#pragma unroll
    for (int d = 64; d >= 1; d >>= 1) {
        if (tid < d) pre[tid] += pre[tid + d];
        __syncthreads();
    }
    int ex_block = pre[0];

    if (gid < n) {
        int off = ex_block + incl - c;     // global exclusive prefix
        g_off[gid]    = off;
        g_cursor[gid] = off;
        g_dinv[gid]   = rsqrtf(1.0f + deg[gid]);   // self-loop folded in
    }
    if (gid == n - 1) g_off[n] = ne;
}

// scatter edges into CSR-by-destination buckets, with precomputed norm
__global__ void k_scatter(const int* __restrict__ ei,
                          const float* __restrict__ w, int ne) {
    int e = blockIdx.x * blockDim.x + threadIdx.x;
    if (e >= ne) return;
    int r = ei[e];
    int c = ei[ne + e];
    float nn = g_dinv[r] * w[e] * g_dinv[c];
    int pos = atomicAdd(&g_cursor[c], 1);
    g_edge[pos] = make_int2(r, __float_as_int(nn));
}

// ---------------- per-layer kernels -----------------------------------------

// y[n,64] = x[n,64] @ W[64,64]; 128 threads, 128-row tile, 8x8 reg tile.
__global__ void __launch_bounds__(128) k_gemm64(
        const float* __restrict__ x,
        const float* __restrict__ W,
        float* __restrict__ y, int n) {
    __shared__ float Ws[64 * 64];     // 16 KB, [k][c]
    __shared__ float xs[64 * 128];    // 32 KB, transposed [k][row_local]
    int tid = threadIdx.x;
    int base = blockIdx.x * 128;

    {
        const float4* Wv = (const float4*)W;
        float4* Wd = (float4*)Ws;
#pragma unroll
        for (int i = 0; i < 8; i++) Wd[tid + 128 * i] = Wv[tid + 128 * i];
    }
    {
        int row = base + tid;
        int rc = (row < n) ? row : (n - 1);
        const float4* xv = (const float4*)(x + (size_t)rc * DIM);
#pragma unroll
        for (int j = 0; j < 16; j++) {
            float4 v = xv[j];
            xs[(j * 4 + 0) * 128 + tid] = v.x;
            xs[(j * 4 + 1) * 128 + tid] = v.y;
            xs[(j * 4 + 2) * 128 + tid] = v.z;
            xs[(j * 4 + 3) * 128 + tid] = v.w;
        }
    }
    __syncthreads();

    int r0 = (tid >> 3) << 3;
    int c0 = (tid & 7) << 3;

    float acc[8][8];
#pragma unroll
    for (int i = 0; i < 8; i++)
#pragma unroll
        for (int j = 0; j < 8; j++) acc[i][j] = 0.0f;

#pragma unroll 2
    for (int k = 0; k < 64; k++) {
        float4 a0 = *(const float4*)&xs[k * 128 + r0];
        float4 a1 = *(const float4*)&xs[k * 128 + r0 + 4];
        float4 b0 = *(const float4*)&Ws[k * 64 + c0];
        float4 b1 = *(const float4*)&Ws[k * 64 + c0 + 4];
        float av[8] = {a0.x, a0.y, a0.z, a0.w, a1.x, a1.y, a1.z, a1.w};
        float bv[8] = {b0.x, b0.y, b0.z, b0.w, b1.x, b1.y, b1.z, b1.w};
#pragma unroll
        for (int i = 0; i < 8; i++)
#pragma unroll
            for (int j = 0; j < 8; j++)
                acc[i][j] = fmaf(av[i], bv[j], acc[i][j]);
    }

#pragma unroll
    for (int i = 0; i < 8; i++) {
        int row = base + r0 + i;
        if (row < n) {
            float4* yp = (float4*)(y + (size_t)row * DIM + c0);
            yp[0] = make_float4(acc[i][0], acc[i][1], acc[i][2], acc[i][3]);
            yp[1] = make_float4(acc[i][4], acc[i][5], acc[i][6], acc[i][7]);
        }
    }
}

// pull aggregation: one warp per node; half-warp per edge, float4 gathers,
// 4 edges in flight per half. Fuses self-loop, bias, 0.9*out + 0.1*prev.
__global__ void k_agg(const float4* __restrict__ xw4,
                      const float4* __restrict__ prev4,
                      float4* __restrict__ dst4,
                      const float4* __restrict__ b4, int n) {
    int warp = (blockIdx.x * blockDim.x + threadIdx.x) >> 5;
    int lane = threadIdx.x & 31;
    if (warp >= n) return;
    int lane16 = lane & 15;
    int half   = lane >> 4;

    float4 acc = make_float4(0.f, 0.f, 0.f, 0.f);
    int s = g_off[warp];
    int e = g_off[warp + 1];

    int i = s + half;
    // 4 edges per half per iteration (8 edges per warp)
    for (; i + 6 < e; i += 8) {
        int2 e0 = g_edge[i];
        int2 e1 = g_edge[i + 2];
        int2 e2 = g_edge[i + 4];
        int2 e3 = g_edge[i + 6];
        float4 v0 = xw4[(size_t)e0.x * 16 + lane16];
        float4 v1 = xw4[(size_t)e1.x * 16 + lane16];
        float4 v2 = xw4[(size_t)e2.x * 16 + lane16];
        float4 v3 = xw4[(size_t)e3.x * 16 + lane16];
        float w0 = __int_as_float(e0.y), w1 = __int_as_float(e1.y);
        float w2 = __int_as_float(e2.y), w3 = __int_as_float(e3.y);
        acc.x = fmaf(v0.x, w0, acc.x); acc.y = fmaf(v0.y, w0, acc.y);
        acc.z = fmaf(v0.z, w0, acc.z); acc.w = fmaf(v0.w, w0, acc.w);
        acc.x = fmaf(v1.x, w1, acc.x); acc.y = fmaf(v1.y, w1, acc.y);
        acc.z = fmaf(v1.z, w1, acc.z); acc.w = fmaf(v1.w, w1, acc.w);
        acc.x = fmaf(v2.x, w2, acc.x); acc.y = fmaf(v2.y, w2, acc.y);
        acc.z = fmaf(v2.z, w2, acc.z); acc.w = fmaf(v2.w, w2, acc.w);
        acc.x = fmaf(v3.x, w3, acc.x); acc.y = fmaf(v3.y, w3, acc.y);
        acc.z = fmaf(v3.z, w3, acc.z); acc.w = fmaf(v3.w, w3, acc.w);
    }
    for (; i < e; i += 2) {
        int2 e0 = g_edge[i];
        float4 v0 = xw4[(size_t)e0.x * 16 + lane16];
        float w0 = __int_as_float(e0.y);
        acc.x = fmaf(v0.x, w0, acc.x); acc.y = fmaf(v0.y, w0, acc.y);
        acc.z = fmaf(v0.z, w0, acc.z); acc.w = fmaf(v0.w, w0, acc.w);
    }

    // combine the two halves
    acc.x += __shfl_xor_sync(0xFFFFFFFFu, acc.x, 16);
    acc.y += __shfl_xor_sync(0xFFFFFFFFu, acc.y, 16);
    acc.z += __shfl_xor_sync(0xFFFFFFFFu, acc.z, 16);
    acc.w += __shfl_xor_sync(0xFFFFFFFFu, acc.w, 16);

    if (half == 0) {
        float di = g_dinv[warp];
        float selfw = di * di;
        float4 sv = xw4[(size_t)warp * 16 + lane16];
        acc.x = fmaf(sv.x, selfw, acc.x);
        acc.y = fmaf(sv.y, selfw, acc.y);
        acc.z = fmaf(sv.z, selfw, acc.z);
        acc.w = fmaf(sv.w, selfw, acc.w);
        float4 bv = b4[lane16];
        float4 pv = prev4[(size_t)warp * 16 + lane16];
        float4 o;
        o.x = 0.9f * (acc.x + bv.x) + 0.1f * pv.x;
        o.y = 0.9f * (acc.y + bv.y) + 0.1f * pv.y;
        o.z = 0.9f * (acc.z + bv.z) + 0.1f * pv.z;
        o.w = 0.9f * (acc.w + bv.w) + 0.1f * pv.w;
        dst4[(size_t)warp * 16 + lane16] = o;
    }
}

// ---------------- launch ------------------------------------------------------

extern "C" void kernel_launch(void* const* d_in, const int* in_sizes, int n_in,
                              void* d_out, int out_size) {
    const float* x    = (const float*)d_in[0];   // [N, 64] fp32
    const int*   ei   = (const int*)d_in[1];     // [2, E] int32
    const float* ew   = (const float*)d_in[2];   // [E] fp32
    const float* W1   = (const float*)d_in[3];
    const float* b1   = (const float*)d_in[4];
    const float* W2   = (const float*)d_in[5];
    const float* b2   = (const float*)d_in[6];
    float*       out  = (float*)d_out;

    const int n  = in_sizes[0] / DIM;   // 100000
    const int ne = in_sizes[1] / 2;     // 1250000

    unsigned char* blob = nullptr;
    float *xw = nullptr, *tmp = nullptr;
    cudaGetSymbolAddress((void**)&blob, g_blob);
    cudaGetSymbolAddress((void**)&xw,   g_xw);
    cudaGetSymbolAddress((void**)&tmp,  g_tmp);

    float* degp = (float*)blob;
    int*   cntp = (int*)(blob + (size_t)n * 4);
    int*   pubp = (int*)(blob + (size_t)n * 8);

    const int T = 256;
    const int gemm_grid = (n + 127) / 128;
    const int agg_grid  = (n * 32 + T - 1) / T;

    // ---- fork: layer-1 GEMM (depends only on x, W1) runs beside the build
    bool forked = g_ss.ok;
    if (forked) {
        cudaEventRecord(g_ss.evFork, 0);
        cudaStreamWaitEvent(g_ss.s, g_ss.evFork, 0);
        k_gemm64<<<gemm_grid, 128, 0, g_ss.s>>>(x, W1, xw, n);
        cudaEventRecord(g_ss.evJoin, g_ss.s);
    }

    // ---- build CSR-by-destination (shared across both layers) ----
    cudaMemsetAsync(blob, 0, (size_t)n * 8 + 512, 0);
    k_deg_cnt <<<(ne + T - 1) / T, T>>>(ei, ew, degp, cntp, ne);
    k_scan_off<<<NUM_SCAN_BLKS, SCAN_BLK>>>(cntp, degp, pubp, n, ne);
    k_scatter <<<(ne + T - 1) / T, T>>>(ei, ew, ne);

    if (forked) {
        cudaStreamWaitEvent(0, g_ss.evJoin, 0);
    } else {
        k_gemm64<<<gemm_grid, 128>>>(x, W1, xw, n);
    }

    // ---- layer 1 aggregation ----
    k_agg<<<agg_grid, T>>>((const float4*)xw, (const float4*)x,
                           (float4*)tmp, (const float4*)b1, n);

    // ---- layer 2 ----
    k_gemm64<<<gemm_grid, 128>>>(tmp, W2, xw, n);
    k_agg<<<agg_grid, T>>>((const float4*)xw, (const float4*)tmp,
                           (float4*)out, (const float4*)b2, n);
}

// round 7
// speedup vs baseline: 1.4012x; 1.4012x over previous
#include <cuda_runtime.h>

#define N_NODES 100000
#define DIM 64
#define N_EDGES 1250000
#define SCAN_BLK 1024
#define NUM_SCAN_BLKS ((N_NODES + SCAN_BLK - 1) / SCAN_BLK)   // 98

// ---------------- scratch (static device globals; no runtime allocation) ----
// zero-blob: [deg: N floats][cnt: N ints] — one memset clears both
__device__ unsigned char g_blob[(size_t)N_NODES * 8];
__device__ float g_dinv[N_NODES];
__device__ int   g_incl[N_NODES];
__device__ int   g_off[N_NODES + 1];
__device__ int   g_cursor[N_NODES];
__device__ int   g_bsum[256];
__device__ int2  g_edge[N_EDGES];          // (src, nrm-as-int) interleaved
__device__ float g_xw[(size_t)N_NODES * DIM];
__device__ float g_tmp[(size_t)N_NODES * DIM];

// ---------------- side stream for fork-join overlap (created at load time) --
struct SideStream {
    cudaStream_t s = nullptr;
    cudaEvent_t  evFork = nullptr, evJoin = nullptr;
    bool ok = false;
    SideStream() {
        ok = (cudaStreamCreateWithFlags(&s, cudaStreamNonBlocking) == cudaSuccess) &&
             (cudaEventCreateWithFlags(&evFork, cudaEventDisableTiming) == cudaSuccess) &&
             (cudaEventCreateWithFlags(&evJoin, cudaEventDisableTiming) == cudaSuccess);
    }
};
static SideStream g_ss;

// ---------------- structure-building kernels (run once per call) ------------

// degree accumulation + in-degree histogram (edge_index int32: [2, E])
__global__ void k_deg_cnt(const int* __restrict__ ei,
                          const float* __restrict__ w,
                          float* __restrict__ deg,
                          int* __restrict__ cnt, int ne) {
    int e = blockIdx.x * blockDim.x + threadIdx.x;
    if (e >= ne) return;
    int c = ei[ne + e];                // col (target)
    atomicAdd(&deg[c], w[e]);
    atomicAdd(&cnt[c], 1);
}

// per-1024-block inclusive scan of cnt
__global__ void k_scan1(const int* __restrict__ cnt, int n) {
    __shared__ int s[SCAN_BLK];
    int gid = blockIdx.x * SCAN_BLK + threadIdx.x;
    int v = (gid < n) ? cnt[gid] : 0;
    s[threadIdx.x] = v;
    __syncthreads();
    for (int d = 1; d < SCAN_BLK; d <<= 1) {
        int t = (threadIdx.x >= d) ? s[threadIdx.x - d] : 0;
        __syncthreads();
        s[threadIdx.x] += t;
        __syncthreads();
    }
    if (gid < n) g_incl[gid] = s[threadIdx.x];
    if (threadIdx.x == SCAN_BLK - 1) g_bsum[blockIdx.x] = s[SCAN_BLK - 1];
}

// exclusive scan of block sums (single block, nb <= 128)
__global__ void k_scan2(int nb) {
    __shared__ int s[128];
    int v = (threadIdx.x < nb) ? g_bsum[threadIdx.x] : 0;
    s[threadIdx.x] = v;
    __syncthreads();
    for (int d = 1; d < 128; d <<= 1) {
        int t = (threadIdx.x >= d) ? s[threadIdx.x - d] : 0;
        __syncthreads();
        s[threadIdx.x] += t;
        __syncthreads();
    }
    if (threadIdx.x < nb) g_bsum[threadIdx.x] = s[threadIdx.x] - v;  // exclusive
}

// final offsets + cursor copy + dinv (self-loop folded in: deg+1)
__global__ void k_scan3(const int* __restrict__ cnt,
                        const float* __restrict__ deg, int n, int ne) {
    int gid = blockIdx.x * blockDim.x + threadIdx.x;
    if (gid < n) {
        int off = g_incl[gid] - cnt[gid] + g_bsum[gid >> 10];  // exclusive
        g_off[gid] = off;
        g_cursor[gid] = off;
        g_dinv[gid] = rsqrtf(1.0f + deg[gid]);
    }
    if (gid == 0) g_off[n] = ne;
}

// scatter edges into CSR-by-destination buckets, with precomputed norm
__global__ void k_scatter(const int* __restrict__ ei,
                          const float* __restrict__ w, int ne) {
    int e = blockIdx.x * blockDim.x + threadIdx.x;
    if (e >= ne) return;
    int r = ei[e];
    int c = ei[ne + e];
    float nn = g_dinv[r] * w[e] * g_dinv[c];
    int pos = atomicAdd(&g_cursor[c], 1);
    g_edge[pos] = make_int2(r, __float_as_int(nn));
}

// ---------------- per-layer kernels -----------------------------------------

// y[n,64] = x[n,64] @ W[64,64]; 128 threads, 128-row tile, 8x8 reg tile.
__global__ void __launch_bounds__(128) k_gemm64(
        const float* __restrict__ x,
        const float* __restrict__ W,
        float* __restrict__ y, int n) {
    __shared__ float Ws[64 * 64];     // 16 KB, [k][c]
    __shared__ float xs[64 * 128];    // 32 KB, transposed [k][row_local]
    int tid = threadIdx.x;
    int base = blockIdx.x * 128;

    {
        const float4* Wv = (const float4*)W;
        float4* Wd = (float4*)Ws;
#pragma unroll
        for (int i = 0; i < 8; i++) Wd[tid + 128 * i] = Wv[tid + 128 * i];
    }
    {
        int row = base + tid;
        int rc = (row < n) ? row : (n - 1);
        const float4* xv = (const float4*)(x + (size_t)rc * DIM);
#pragma unroll
        for (int j = 0; j < 16; j++) {
            float4 v = xv[j];
            xs[(j * 4 + 0) * 128 + tid] = v.x;
            xs[(j * 4 + 1) * 128 + tid] = v.y;
            xs[(j * 4 + 2) * 128 + tid] = v.z;
            xs[(j * 4 + 3) * 128 + tid] = v.w;
        }
    }
    __syncthreads();

    int r0 = (tid >> 3) << 3;
    int c0 = (tid & 7) << 3;

    float acc[8][8];
#pragma unroll
    for (int i = 0; i < 8; i++)
#pragma unroll
        for (int j = 0; j < 8; j++) acc[i][j] = 0.0f;

#pragma unroll 2
    for (int k = 0; k < 64; k++) {
        float4 a0 = *(const float4*)&xs[k * 128 + r0];
        float4 a1 = *(const float4*)&xs[k * 128 + r0 + 4];
        float4 b0 = *(const float4*)&Ws[k * 64 + c0];
        float4 b1 = *(const float4*)&Ws[k * 64 + c0 + 4];
        float av[8] = {a0.x, a0.y, a0.z, a0.w, a1.x, a1.y, a1.z, a1.w};
        float bv[8] = {b0.x, b0.y, b0.z, b0.w, b1.x, b1.y, b1.z, b1.w};
#pragma unroll
        for (int i = 0; i < 8; i++)
#pragma unroll
            for (int j = 0; j < 8; j++)
                acc[i][j] = fmaf(av[i], bv[j], acc[i][j]);
    }

#pragma unroll
    for (int i = 0; i < 8; i++) {
        int row = base + r0 + i;
        if (row < n) {
            float4* yp = (float4*)(y + (size_t)row * DIM + c0);
            yp[0] = make_float4(acc[i][0], acc[i][1], acc[i][2], acc[i][3]);
            yp[1] = make_float4(acc[i][4], acc[i][5], acc[i][6], acc[i][7]);
        }
    }
}

// pull aggregation: one warp per node; half-warp per edge (lanes 0-15 edge i,
// lanes 16-31 edge i+1), float4 gathers, int2 edge records. Fuses self-loop,
// bias, temp = 0.9*out + 0.1*prev.
__global__ void k_agg(const float4* __restrict__ xw4,
                      const float4* __restrict__ prev4,
                      float4* __restrict__ dst4,
                      const float4* __restrict__ b4, int n) {
    int warp = (blockIdx.x * blockDim.x + threadIdx.x) >> 5;
    int lane = threadIdx.x & 31;
    if (warp >= n) return;
    int lane16 = lane & 15;
    int half   = lane >> 4;

    float4 acc = make_float4(0.f, 0.f, 0.f, 0.f);
    int s = g_off[warp];
    int e = g_off[warp + 1];

    int i = s + half;
    // 2x unrolled (each step covers this half's edges i and i+2)
    for (; i + 2 < e; i += 4) {
        int2 e0 = g_edge[i];
        int2 e1 = g_edge[i + 2];
        float4 v0 = xw4[(size_t)e0.x * 16 + lane16];
        float4 v1 = xw4[(size_t)e1.x * 16 + lane16];
        float w0 = __int_as_float(e0.y);
        float w1 = __int_as_float(e1.y);
        acc.x = fmaf(v0.x, w0, acc.x); acc.y = fmaf(v0.y, w0, acc.y);
        acc.z = fmaf(v0.z, w0, acc.z); acc.w = fmaf(v0.w, w0, acc.w);
        acc.x = fmaf(v1.x, w1, acc.x); acc.y = fmaf(v1.y, w1, acc.y);
        acc.z = fmaf(v1.z, w1, acc.z); acc.w = fmaf(v1.w, w1, acc.w);
    }
    if (i < e) {
        int2 e0 = g_edge[i];
        float4 v0 = xw4[(size_t)e0.x * 16 + lane16];
        float w0 = __int_as_float(e0.y);
        acc.x = fmaf(v0.x, w0, acc.x); acc.y = fmaf(v0.y, w0, acc.y);
        acc.z = fmaf(v0.z, w0, acc.z); acc.w = fmaf(v0.w, w0, acc.w);
    }

    // combine the two halves
    acc.x += __shfl_xor_sync(0xFFFFFFFFu, acc.x, 16);
    acc.y += __shfl_xor_sync(0xFFFFFFFFu, acc.y, 16);
    acc.z += __shfl_xor_sync(0xFFFFFFFFu, acc.z, 16);
    acc.w += __shfl_xor_sync(0xFFFFFFFFu, acc.w, 16);

    if (half == 0) {
        float di = g_dinv[warp];
        float selfw = di * di;
        float4 sv = xw4[(size_t)warp * 16 + lane16];
        acc.x = fmaf(sv.x, selfw, acc.x);
        acc.y = fmaf(sv.y, selfw, acc.y);
        acc.z = fmaf(sv.z, selfw, acc.z);
        acc.w = fmaf(sv.w, selfw, acc.w);
        float4 bv = b4[lane16];
        float4 pv = prev4[(size_t)warp * 16 + lane16];
        float4 o;
        o.x = 0.9f * (acc.x + bv.x) + 0.1f * pv.x;
        o.y = 0.9f * (acc.y + bv.y) + 0.1f * pv.y;
        o.z = 0.9f * (acc.z + bv.z) + 0.1f * pv.z;
        o.w = 0.9f * (acc.w + bv.w) + 0.1f * pv.w;
        dst4[(size_t)warp * 16 + lane16] = o;
    }
}

// ---------------- launch ------------------------------------------------------

extern "C" void kernel_launch(void* const* d_in, const int* in_sizes, int n_in,
                              void* d_out, int out_size) {
    const float* x    = (const float*)d_in[0];   // [N, 64] fp32
    const int*   ei   = (const int*)d_in[1];     // [2, E] int32
    const float* ew   = (const float*)d_in[2];   // [E] fp32
    const float* W1   = (const float*)d_in[3];
    const float* b1   = (const float*)d_in[4];
    const float* W2   = (const float*)d_in[5];
    const float* b2   = (const float*)d_in[6];
    float*       out  = (float*)d_out;

    const int n  = in_sizes[0] / DIM;   // 100000
    const int ne = in_sizes[1] / 2;     // 1250000

    unsigned char* blob = nullptr;
    float *xw = nullptr, *tmp = nullptr;
    cudaGetSymbolAddress((void**)&blob, g_blob);
    cudaGetSymbolAddress((void**)&xw,   g_xw);
    cudaGetSymbolAddress((void**)&tmp,  g_tmp);

    float* degp = (float*)blob;
    int*   cntp = (int*)(blob + (size_t)n * 4);

    const int T = 256;
    const int gemm_grid = (n + 127) / 128;
    const int agg_grid  = (n * 32 + T - 1) / T;

    // ---- fork: layer-1 GEMM (depends only on x, W1) runs beside the build
    bool forked = g_ss.ok;
    if (forked) {
        cudaEventRecord(g_ss.evFork, 0);
        cudaStreamWaitEvent(g_ss.s, g_ss.evFork, 0);
        k_gemm64<<<gemm_grid, 128, 0, g_ss.s>>>(x, W1, xw, n);
        cudaEventRecord(g_ss.evJoin, g_ss.s);
    }

    // ---- build CSR-by-destination (shared across both layers) ----
    cudaMemsetAsync(blob, 0, (size_t)n * 8, 0);
    k_deg_cnt<<<(ne + T - 1) / T, T>>>(ei, ew, degp, cntp, ne);
    k_scan1  <<<NUM_SCAN_BLKS, SCAN_BLK>>>(cntp, n);
    k_scan2  <<<1, 128>>>(NUM_SCAN_BLKS);
    k_scan3  <<<(n + T - 1) / T, T>>>(cntp, degp, n, ne);
    k_scatter<<<(ne + T - 1) / T, T>>>(ei, ew, ne);

    if (forked) {
        cudaStreamWaitEvent(0, g_ss.evJoin, 0);
    } else {
        k_gemm64<<<gemm_grid, 128>>>(x, W1, xw, n);
    }

    // ---- layer 1 aggregation ----
    k_agg<<<agg_grid, T>>>((const float4*)xw, (const float4*)x,
                           (float4*)tmp, (const float4*)b1, n);

    // ---- layer 2 ----
    k_gemm64<<<gemm_grid, 128>>>(tmp, W2, xw, n);
    k_agg<<<agg_grid, T>>>((const float4*)xw, (const float4*)tmp,
                           (float4*)out, (const float4*)b2, n);
}